// round 3
// baseline (speedup 1.0000x reference)
#include <cuda_runtime.h>
#include <stdint.h>

// z[e, :] = h[src[e], :] * h[dst[e], :]
// h: [N=50000, D=64] fp32, src/dst: [E=800000] int32 (JAX x64 disabled
// downcasts the requested int64 to int32), out: [E, 64] fp32.
// One thread per float4 (16B): 16 threads per 256B edge row.
// h (12.8 MB) fits in L2 -> gathers are L2 hits; LTS byte cap (~6300 B/cyc)
// is the expected ceiling.

static constexpr int D = 64;
static constexpr int VEC_PER_ROW = D / 4;  // 16 float4 per row

__global__ void __launch_bounds__(256, 8) u_mul_v_kernel(
    const float4* __restrict__ h,        // [N, 16] as float4
    const int* __restrict__ src,         // [E] int32
    const int* __restrict__ dst,         // [E] int32
    float4* __restrict__ out,            // [E, 16] as float4
    int n_edges,
    int n_nodes)
{
    const long long tid = (long long)blockIdx.x * blockDim.x + threadIdx.x;
    const long long total = (long long)n_edges * VEC_PER_ROW;
    if (tid >= total) return;

    const int e = (int)(tid >> 4);       // tid / 16
    const int j = (int)(tid & 15);       // tid % 16

    // 16 adjacent threads read the same index -> L1 broadcast.
    int s = __ldg(&src[e]);
    int d = __ldg(&dst[e]);

    // Defensive clamp: if dtype assumption is wrong we get rel_err fail
    // (diagnosable) instead of an illegal access. Free when correct.
    s = min(max(s, 0), n_nodes - 1);
    d = min(max(d, 0), n_nodes - 1);

    const float4 a = __ldg(&h[(long long)s * VEC_PER_ROW + j]);
    const float4 b = __ldg(&h[(long long)d * VEC_PER_ROW + j]);

    float4 r;
    r.x = a.x * b.x;
    r.y = a.y * b.y;
    r.z = a.z * b.z;
    r.w = a.w * b.w;

    out[tid] = r;
}

extern "C" void kernel_launch(void* const* d_in, const int* in_sizes, int n_in,
                              void* d_out, int out_size) {
    const float4* h = (const float4*)d_in[0];
    const int* src = (const int*)d_in[1];
    const int* dst = (const int*)d_in[2];
    float4* out = (float4*)d_out;

    const int n_edges = in_sizes[1];          // E = 800000
    const int n_nodes = in_sizes[0] / D;      // N = 50000
    const long long total = (long long)n_edges * VEC_PER_ROW;
    const int threads = 256;
    const int blocks = (int)((total + threads - 1) / threads);

    u_mul_v_kernel<<<blocks, threads>>>(h, src, dst, out, n_edges, n_nodes);
}

// round 4
// speedup vs baseline: 1.5216x; 1.5216x over previous
#include <cuda_runtime.h>
#include <stdint.h>

// z[e, :] = h[src[e], :] * h[dst[e], :]
// h: [N=50000, D=64] fp32 (12.8 MB, L2-resident), src/dst: [E=800000] int32,
// out: [E, 64] fp32 (204.8 MB stream).
// Bound by the measured LTS cap (~6300 B/cyc): ~620 MB of L2 traffic -> ~52us
// floor. 8 threads/edge x 2 float4 each: fewer index loads, 2x MLP/thread.
// __stcs stores keep the output stream from evicting h out of L2.

static constexpr int D = 64;
static constexpr int VEC_PER_ROW = D / 4;   // 16 float4 per row
static constexpr int THREADS_PER_EDGE = 8;  // 2 float4 per thread

__global__ void __launch_bounds__(256, 8) u_mul_v_kernel(
    const float4* __restrict__ h,        // [N, 16] as float4
    const int* __restrict__ src,         // [E] int32
    const int* __restrict__ dst,         // [E] int32
    float4* __restrict__ out,            // [E, 16] as float4
    int n_edges)
{
    const int t = blockIdx.x * 256 + threadIdx.x;
    const int e = t >> 3;                // edge id
    const int j = t & 7;                 // float4 pair id within row
    if (e >= n_edges) return;

    // 8 adjacent threads read the same index -> single line, L1 broadcast.
    const int s = __ldg(&src[e]);
    const int d = __ldg(&dst[e]);

    const float4* __restrict__ hs = h + (size_t)s * VEC_PER_ROW;
    const float4* __restrict__ hd = h + (size_t)d * VEC_PER_ROW;

    // Two independent load pairs -> 4 outstanding LDG.128 per thread.
    const float4 a0 = __ldg(hs + j);
    const float4 b0 = __ldg(hd + j);
    const float4 a1 = __ldg(hs + j + 8);
    const float4 b1 = __ldg(hd + j + 8);

    float4 r0, r1;
    r0.x = a0.x * b0.x; r0.y = a0.y * b0.y;
    r0.z = a0.z * b0.z; r0.w = a0.w * b0.w;
    r1.x = a1.x * b1.x; r1.y = a1.y * b1.y;
    r1.z = a1.z * b1.z; r1.w = a1.w * b1.w;

    float4* o = out + (size_t)e * VEC_PER_ROW + j;
    __stcs(o, r0);          // streaming: don't let output evict h from L2
    __stcs(o + 8, r1);
}

extern "C" void kernel_launch(void* const* d_in, const int* in_sizes, int n_in,
                              void* d_out, int out_size) {
    const float4* h = (const float4*)d_in[0];
    const int* src = (const int*)d_in[1];
    const int* dst = (const int*)d_in[2];
    float4* out = (float4*)d_out;

    const int n_edges = in_sizes[1];  // E = 800000
    const long long total = (long long)n_edges * THREADS_PER_EDGE;
    const int threads = 256;
    const int blocks = (int)((total + threads - 1) / threads);

    u_mul_v_kernel<<<blocks, threads>>>(h, src, dst, out, n_edges);
}